// round 14
// baseline (speedup 1.0000x reference)
#include <cuda_runtime.h>
#include <math.h>
#include <stdint.h>

#define Nn 4096
#define Mm 4096
#define LAMDA 0.01f
#define STOP_THR 1e-7
#define MAX_ITER 100
#define NB 128
#define NTC 256    // CK threads
#define NTS 1024   // sink/epi threads
#define NWS 32     // sink/epi warps
#define S2 70      // smem row stride (floats), even (8B smem accesses)

typedef unsigned long long ull;

// ---------------- device globals ----------------
__device__ float  g_K[(size_t)Nn * Mm];   // 64 MB fp32 K (L2-resident)
__device__ float  g_a[2][Nn];
__device__ float  g_b[2][Mm];
__device__ double g_bdisp[NB];
__device__ double g_bcost[NB];
__device__ int    g_final;
__device__ unsigned g_bar_cnt;     // monotonic
__device__ unsigned g_epi_ticket;  // monotonic

// ---------------- fast exp: FFMA-only ----------------
__device__ __forceinline__ float fexp(float xx) {
    float t  = fmaf(xx, 1.4426950408889634f, 12582912.0f);
    int   n  = __float_as_int(t) - 0x4B400000;
    float fn = t - 12582912.0f;
    float r  = fmaf(fn, -0.693145751953125f, xx);
    r        = fmaf(fn, -1.42860677e-6f, r);
    float p  = 1.3888890e-3f;
    p = fmaf(p, r, 8.3333338e-3f);
    p = fmaf(p, r, 4.1666668e-2f);
    p = fmaf(p, r, 1.6666667e-1f);
    p = fmaf(p, r, 5.0000000e-1f);
    p = fmaf(p, r, 1.0f);
    p = fmaf(p, r, 1.0f);
    return __int_as_float(__float_as_int(p) + (n << 23));
}

#define FMA2(d, a, b) \
    asm("fma.rn.f32x2 %0, %1, %2, %0;" : "+l"(d) : "l"(a), "l"(b))
#define MUL2(d, a, b) \
    asm("mul.rn.f32x2 %0, %1, %2;" : "=l"(d) : "l"(a), "l"(b))
#define UNPACK2(lo, hi, v) \
    asm("mov.b64 {%0, %1}, %2;" : "=f"(lo), "=f"(hi) : "l"(v))

// ------------- cheap acquire/release grid barrier -------
__device__ __forceinline__ void red_rel_add1(unsigned* p) {
    asm volatile("red.release.gpu.global.add.u32 [%0], 1;" :: "l"(p) : "memory");
}
__device__ __forceinline__ unsigned ld_acq(unsigned* p) {
    unsigned v;
    asm volatile("ld.acquire.gpu.global.u32 %0, [%1];" : "=r"(v) : "l"(p) : "memory");
    return v;
}
__device__ __forceinline__ void gbar(unsigned target) {
    __syncthreads();
    if (threadIdx.x == 0) {
        red_rel_add1(&g_bar_cnt);
        while ((int)(ld_acq(&g_bar_cnt) - target) < 0) { }
    }
    __syncthreads();
}

// ===================== Kernel 1: CK build (8x8 tile, NT=256) ==============
// Block: 128 rows x 8 j-tiles of 128.  Thread: 8 rows x 8 cols.
// Per k-pair: 16 LDS.64 feed 64 FFMA2 (1.0 B smem/MAC).
// xp: half-warp broadcast (2 addrs).  yp: 16 lanes stride-6 banks, conflict-free.
__global__ void __launch_bounds__(NTC, 1)
ck_kernel(const float* __restrict__ x, const float* __restrict__ y) {
    extern __shared__ float sm[];
    float* XS = sm;                 // [128][S2]
    float* YS = sm + 128 * S2;      // [128][S2]
    float* xn = YS + 128 * S2;      // [128]
    float* yn = xn + 128;           // [128]

    const int tid = threadIdx.x, blk = blockIdx.x;
    const int lane = tid & 31, warp = tid >> 5;

    if (tid < 32) {
        g_a[0][blk * 32 + tid] = 1.0f / (float)Nn;
        g_b[0][blk * 32 + tid] = 1.0f;
    }

    const int i0 = (blk >> 2) * 128;
    for (int t = tid; t < 4096; t += NTC) {
        int r = t >> 5, c = t & 31;
        float2 v = __ldg((const float2*)(x + (size_t)(i0 + r) * 64) + c);
        *(float2*)(XS + r * S2 + 2 * c) = v;
    }
    __syncthreads();
    if (tid < 128) {
        float s = 0.f;
        #pragma unroll
        for (int k = 0; k < 64; k++) { float v = XS[tid * S2 + k]; s = fmaf(v, v, s); }
        xn[tid] = s;
    }

    const int iy = warp * 16 + (lane >> 4) * 8;   // 8 rows per thread
    const int jx = lane & 15;                     // col base within 16

    for (int s = 0; s < 8; s++) {
        const int j0 = ((blk & 3) * 8 + s) * 128;
        __syncthreads();
        for (int t = tid; t < 4096; t += NTC) {
            int r = t >> 5, c = t & 31;
            float2 v = __ldg((const float2*)(y + (size_t)(j0 + r) * 64) + c);
            *(float2*)(YS + r * S2 + 2 * c) = v;
        }
        __syncthreads();
        if (tid < 128) {
            float sv = 0.f;
            #pragma unroll
            for (int k = 0; k < 64; k++) { float v = YS[tid * S2 + k]; sv = fmaf(v, v, sv); }
            yn[tid] = sv;
        }
        __syncthreads();

        ull acc[8][8];
        #pragma unroll
        for (int u = 0; u < 8; u++)
            #pragma unroll
            for (int w = 0; w < 8; w++) acc[u][w] = 0ULL;

        #pragma unroll 2
        for (int kp = 0; kp < 32; kp++) {
            const int k = kp * 2;
            ull xp[8], yp[8];
            #pragma unroll
            for (int u = 0; u < 8; u++)
                xp[u] = *(const ull*)(XS + (iy + u) * S2 + k);
            #pragma unroll
            for (int w = 0; w < 8; w++)
                yp[w] = *(const ull*)(YS + (jx + 16 * w) * S2 + k);
            #pragma unroll
            for (int u = 0; u < 8; u++)
                #pragma unroll
                for (int w = 0; w < 8; w++)
                    FMA2(acc[u][w], xp[u], yp[w]);
        }

        #pragma unroll
        for (int u = 0; u < 8; u++) {
            const int i = i0 + iy + u;
            const float xni = xn[iy + u];
            #pragma unroll
            for (int w = 0; w < 8; w++) {
                const int jl = jx + 16 * w;
                float lo, hi;
                UNPACK2(lo, hi, acc[u][w]);
                float Cv = xni + yn[jl] - 2.0f * (lo + hi);
                g_K[(size_t)i * Mm + j0 + jl] = fexp(-LAMDA * Cv);
            }
        }
    }
}

// ===================== Kernel 2: Sinkhorn loop (NT=1024) ===================
__global__ void __launch_bounds__(NTS, 1)
sink_kernel(const float* __restrict__ mu, const float* __restrict__ nu) {
    __shared__ float  sA[Nn];
    __shared__ float  sB[Mm];
    __shared__ float  sred[NWS][33];
    __shared__ double sRow[NWS];
    __shared__ double sDS1[NWS];
    __shared__ double sDisp;

    const int tid = threadIdx.x, blk = blockIdx.x;
    const int warp = tid >> 5, lane = tid & 31;
    const unsigned FULL = 0xffffffffu;
    const unsigned base = __ldcg(&g_bar_cnt);
    unsigned gen = 0;
    int fpar = 0;

    for (int it = 0; it < MAX_ITER; ++it) {
        const int cur = it & 1, nxt = cur ^ 1;

        if (it > 0) {       // deferred convergence check on it-1
            if (warp == 0) {
                double sd = __ldcg(&g_bdisp[lane])      + __ldcg(&g_bdisp[lane + 32])
                          + __ldcg(&g_bdisp[lane + 64]) + __ldcg(&g_bdisp[lane + 96]);
                #pragma unroll
                for (int off = 16; off; off >>= 1)
                    sd += __shfl_down_sync(FULL, sd, off);
                if (lane == 0) sDisp = sd;
            }
            __syncthreads();
            if (sDisp <= STOP_THR) { fpar = cur; break; }
            __syncthreads();
        }

        // ---- Phase A: b[nxt] = nu / (K^T a[cur])
        for (int i = tid; i < Nn; i += NTS) sA[i] = __ldcg(&g_a[cur][i]);
        __syncthreads();
        {
            const int j = blk * 32 + lane;
            const float* Kc = g_K + j;
            float acc[8];
            #pragma unroll
            for (int u = 0; u < 8; u++) acc[u] = 0.f;
            for (int ib = 0; ib < Nn; ib += 256) {
                #pragma unroll
                for (int u = 0; u < 8; u++) {
                    const int i = ib + warp + 32 * u;
                    acc[u] = fmaf(Kc[(size_t)i * Mm], sA[i], acc[u]);
                }
            }
            float s = ((acc[0] + acc[1]) + (acc[2] + acc[3]))
                    + ((acc[4] + acc[5]) + (acc[6] + acc[7]));
            sred[warp][lane] = s;
        }
        __syncthreads();
        if (warp == 0) {
            float s = 0.f;
            #pragma unroll
            for (int w = 0; w < NWS; ++w) s += sred[w][lane];
            int j = blk * 32 + lane;
            g_b[nxt][j] = __ldg(&nu[j]) / s;
        }
        gbar(base + (++gen) * NB);

        // ---- Phase B: a[nxt] = mu/(K b_new) + fused disp (1 row per warp)
        for (int i = tid; i < Mm; i += NTS) sA[i] = __ldcg(&g_b[nxt][i]);
        for (int i = tid; i < Mm; i += NTS) sB[i] = __ldcg(&g_b[cur][i]);
        __syncthreads();
        {
            const int i = blk * 32 + warp;
            const ull* K2 = (const ull*)(g_K + (size_t)i * Mm);
            const ull* A2 = (const ull*)sA;
            const ull* B2 = (const ull*)sB;
            ull t = 0ULL, s1 = 0ULL, s2 = 0ULL;
            #pragma unroll 4
            for (int j = lane; j < Mm / 2; j += 32) {
                ull k = K2[j], bn = A2[j], be = B2[j];
                ull k2, tmp;
                MUL2(k2, k, k);
                FMA2(t, k, bn);
                MUL2(tmp, k2, bn);
                FMA2(s1, tmp, bn);
                FMA2(s2, tmp, be);
            }
            float l, h;
            UNPACK2(l, h, t);  float tf  = l + h;
            UNPACK2(l, h, s1); float s1f = l + h;
            UNPACK2(l, h, s2); float s2f = l + h;
            #pragma unroll
            for (int off = 16; off; off >>= 1) {
                tf  += __shfl_down_sync(FULL, tf,  off);
                s1f += __shfl_down_sync(FULL, s1f, off);
                s2f += __shfl_down_sync(FULL, s2f, off);
            }
            if (lane == 0) {
                float an = __ldg(&mu[i]) / tf;
                g_a[nxt][i] = an;
                double dan = (double)an;
                double dao = (double)__ldcg(&g_a[cur][i]);
                double dS1 = dan * dan * (double)s1f;
                double d = (it == 0)
                    ? dS1
                    : dS1 - 2.0 * dan * dao * (double)s2f + sDS1[warp];
                sDS1[warp] = dS1;
                sRow[warp] = d;
            }
        }
        __syncthreads();
        if (tid == 0) {
            double s = 0.0;
            #pragma unroll
            for (int q = 0; q < NWS; ++q) s += sRow[q];
            g_bdisp[blk] = s;
        }
        fpar = nxt;
        gbar(base + (++gen) * NB);
    }

    if (blk == 0 && tid == 0) g_final = fpar;
}

// ===================== Kernel 3: epilogue + last-block cost reduce ========
__global__ void __launch_bounds__(NTS, 1)
epi_kernel(float* __restrict__ out) {
    __shared__ float  sA[Mm];
    __shared__ float  sB[Mm];
    __shared__ double sRow[NWS];
    __shared__ int    sLast;

    const int tid = threadIdx.x, blk = blockIdx.x;
    const int warp = tid >> 5, lane = tid & 31;
    const unsigned FULL = 0xffffffffu;
    const int fpar = __ldcg(&g_final);

    float* Pout = out + 1;
    float* Cmat = out + 1 + (size_t)Nn * Mm;

    for (int i = tid; i < Mm; i += NTS) sA[i] = __ldcg(&g_b[fpar][i]);
    __syncthreads();
    for (int m = tid; m < Mm - 3; m += NTS) sB[m] = sA[m + 3];
    __syncthreads();
    const float4* Bsh4 = (const float4*)sB;

    {
        const int i = blk * 32 + warp;           // 1 row per warp
        const float ai = __ldcg(&g_a[fpar][i]);
        const float*  Kr = g_K + (size_t)i * Mm;
        const float4* K4 = (const float4*)Kr;
        float* Pr = Pout + (size_t)i * Mm;
        float* Cr = Cmat + (size_t)i * Mm;
        float csum = 0.f;

        if (lane < 3) {                  // head j = 0,1,2
            float k = Kr[lane];
            float p = ai * k * sA[lane];
            float c = -69.31471805599453f * __log2f(k);
            __stcs(Pr + lane, p);
            __stcs(Cr + lane, c);
            csum = fmaf(p, c, csum);
        }

        float4 curr = K4[lane];
        for (int s = 0; s < 32; s++) {
            const int q = lane + 32 * s;
            const int nidx = (s < 31) ? (lane + 32 * (s + 1)) : lane;
            float4 newq = K4[nidx];
            float nx = __shfl_down_sync(FULL, curr.x, 1);
            float ny = __shfl_down_sync(FULL, curr.y, 1);
            float nz = __shfl_down_sync(FULL, curr.z, 1);
            float bx = __shfl_sync(FULL, newq.x, 0);
            float by = __shfl_sync(FULL, newq.y, 0);
            float bz = __shfl_sync(FULL, newq.z, 0);
            if (lane == 31) { nx = bx; ny = by; nz = bz; }

            if (q <= 1022) {
                const int jst = 4 * q + 3;
                float k0 = curr.w, k1 = nx, k2 = ny, k3 = nz;
                float4 bq = Bsh4[q];
                float p0 = ai * k0 * bq.x, p1 = ai * k1 * bq.y;
                float p2 = ai * k2 * bq.z, p3 = ai * k3 * bq.w;
                float c0 = -69.31471805599453f * __log2f(k0);
                float c1 = -69.31471805599453f * __log2f(k1);
                float c2 = -69.31471805599453f * __log2f(k2);
                float c3 = -69.31471805599453f * __log2f(k3);
                float4 pq; pq.x = p0; pq.y = p1; pq.z = p2; pq.w = p3;
                float4 cq; cq.x = c0; cq.y = c1; cq.z = c2; cq.w = c3;
                __stcs((float4*)(Pr + jst), pq);
                __stcs((float4*)(Cr + jst), cq);
                csum = fmaf(p0, c0, csum); csum = fmaf(p1, c1, csum);
                csum = fmaf(p2, c2, csum); csum = fmaf(p3, c3, csum);
            }
            if (s == 31 && lane == 31) {  // tail j = 4095
                float k = curr.w;
                float p = ai * k * sA[4095];
                float c = -69.31471805599453f * __log2f(k);
                __stcs(Pr + 4095, p);
                __stcs(Cr + 4095, c);
                csum = fmaf(p, c, csum);
            }
            curr = newq;
        }

        #pragma unroll
        for (int off = 16; off; off >>= 1)
            csum += __shfl_down_sync(FULL, csum, off);
        if (lane == 0) sRow[warp] = (double)csum;
    }
    __syncthreads();
    if (tid == 0) {
        double s = 0.0;
        #pragma unroll
        for (int q = 0; q < NWS; ++q) s += sRow[q];
        g_bcost[blk] = s;
        __threadfence();
        unsigned old;
        asm volatile("atom.global.add.u32 %0, [%1], 1;"
                     : "=r"(old) : "l"(&g_epi_ticket) : "memory");
        sLast = ((old + 1) % NB == 0);
    }
    __syncthreads();
    if (sLast) {
        __threadfence();
        if (warp == 0) {
            double sc = __ldcg(&g_bcost[lane])      + __ldcg(&g_bcost[lane + 32])
                      + __ldcg(&g_bcost[lane + 64]) + __ldcg(&g_bcost[lane + 96]);
            #pragma unroll
            for (int off = 16; off; off >>= 1)
                sc += __shfl_down_sync(FULL, sc, off);
            if (lane == 0) out[0] = (float)sc;
        }
    }
}

// ---------------- launch ----------------
extern "C" void kernel_launch(void* const* d_in, const int* in_sizes, int n_in,
                              void* d_out, int out_size) {
    const float* x  = (const float*)d_in[0];
    const float* y  = (const float*)d_in[1];
    const float* mu = (const float*)d_in[2];
    const float* nu = (const float*)d_in[3];
    float* out = (float*)d_out;

    const int ck_smem = (256 * S2 + 256) * (int)sizeof(float);
    cudaFuncSetAttribute(ck_kernel, cudaFuncAttributeMaxDynamicSharedMemorySize, ck_smem);

    ck_kernel<<<NB, NTC, ck_smem>>>(x, y);
    sink_kernel<<<NB, NTS>>>(mu, nu);
    epi_kernel<<<NB, NTS>>>(out);
}

// round 15
// speedup vs baseline: 1.1789x; 1.1789x over previous
#include <cuda_runtime.h>
#include <math.h>
#include <stdint.h>

#define Nn 4096
#define Mm 4096
#define LAMDA 0.01f
#define STOP_THR 1e-7
#define MAX_ITER 100
#define NB 128
#define NTC 512    // CK threads
#define NTS 1024   // sink/epi threads
#define NWS 32     // sink/epi warps

typedef unsigned long long ull;

// ---------------- device globals ----------------
__device__ float  g_K[(size_t)Nn * Mm];   // 64 MB fp32 K (L2-resident)
__device__ float  g_a[2][Nn];
__device__ float  g_b[2][Mm];
__device__ double g_bdisp[NB];
__device__ double g_bcost[NB];
__device__ int    g_final;
__device__ unsigned g_bar_cnt;     // monotonic
__device__ unsigned g_epi_ticket;  // monotonic

// ---------------- fast exp: FFMA-only ----------------
__device__ __forceinline__ float fexp(float xx) {
    float t  = fmaf(xx, 1.4426950408889634f, 12582912.0f);
    int   n  = __float_as_int(t) - 0x4B400000;
    float fn = t - 12582912.0f;
    float r  = fmaf(fn, -0.693145751953125f, xx);
    r        = fmaf(fn, -1.42860677e-6f, r);
    float p  = 1.3888890e-3f;
    p = fmaf(p, r, 8.3333338e-3f);
    p = fmaf(p, r, 4.1666668e-2f);
    p = fmaf(p, r, 1.6666667e-1f);
    p = fmaf(p, r, 5.0000000e-1f);
    p = fmaf(p, r, 1.0f);
    p = fmaf(p, r, 1.0f);
    return __int_as_float(__float_as_int(p) + (n << 23));
}

#define FMA2(d, a, b) \
    asm("fma.rn.f32x2 %0, %1, %2, %0;" : "+l"(d) : "l"(a), "l"(b))
#define MUL2(d, a, b) \
    asm("mul.rn.f32x2 %0, %1, %2;" : "=l"(d) : "l"(a), "l"(b))
#define UNPACK2(lo, hi, v) \
    asm("mov.b64 {%0, %1}, %2;" : "=f"(lo), "=f"(hi) : "l"(v))
#define CVT_TF32(d, f) \
    asm("cvt.rna.tf32.f32 %0, %1;" : "=r"(d) : "f"(f))

// ------------- cheap acquire/release grid barrier -------
__device__ __forceinline__ void red_rel_add1(unsigned* p) {
    asm volatile("red.release.gpu.global.add.u32 [%0], 1;" :: "l"(p) : "memory");
}
__device__ __forceinline__ unsigned ld_acq(unsigned* p) {
    unsigned v;
    asm volatile("ld.acquire.gpu.global.u32 %0, [%1];" : "=r"(v) : "l"(p) : "memory");
    return v;
}
__device__ __forceinline__ void gbar(unsigned target) {
    __syncthreads();
    if (threadIdx.x == 0) {
        red_rel_add1(&g_bar_cnt);
        while ((int)(ld_acq(&g_bar_cnt) - target) < 0) { }
    }
    __syncthreads();
}

// ===================== Kernel 1: CK build via tensor cores (tf32 MMA) =====
// Block: 128 rows (i0) x 1024 cols (jbase), 8 col-stages of 128.
// Warp w: row-tile rw=w>>1 (16 rows), col-half ch=w&1 (8 of 16 n8-tiles/stage).
// A/B staged in fragment order (tf32) -> inner loop: LDS.64 + mma.m16n8k8.
__global__ void __launch_bounds__(NTC, 1)
ck_kernel(const float* __restrict__ x, const float* __restrict__ y) {
    extern __shared__ unsigned smu[];
    unsigned* AP = smu;                  // [8 rw][8 kk][32 lane][4 reg] = 8192
    unsigned* BP = smu + 8192;           // [16 t][8 kk][32 lane][2 reg] = 8192
    float* sxn = (float*)(smu + 16384);  // [128]
    float* syn = sxn + 128;              // [128]

    const int tid = threadIdx.x, blk = blockIdx.x;
    const int lane = tid & 31, warp = tid >> 5;
    const int gid = lane >> 2, tig = lane & 3;

    if (tid < 32) {
        g_a[0][blk * 32 + tid] = 1.0f / (float)Nn;
        g_b[0][blk * 32 + tid] = 1.0f;
    }

    const int i0 = (blk >> 2) * 128;
    const int jbase = (blk & 3) * 1024;

    // ---- pack A fragments (once) + xn
    for (int e = tid; e < 8192; e += NTC) {
        const int r = e >> 6, c = e & 63;
        float v = __ldg(x + (size_t)(i0 + r) * 64 + c);
        unsigned tv; CVT_TF32(tv, v);
        const int rw = r >> 4, ri = r & 15, kk = c >> 3, rem = c & 7;
        const int reg = (ri >> 3) + 2 * (rem >> 2);
        const int ln = (ri & 7) * 4 + (rem & 3);
        AP[((rw * 8 + kk) * 32 + ln) * 4 + reg] = tv;
    }
    if (tid < 128) {
        const float4* xr = (const float4*)(x + (size_t)(i0 + tid) * 64);
        float s = 0.f;
        #pragma unroll
        for (int q = 0; q < 16; q++) {
            float4 v = __ldg(xr + q);
            s = fmaf(v.x, v.x, s); s = fmaf(v.y, v.y, s);
            s = fmaf(v.z, v.z, s); s = fmaf(v.w, v.w, s);
        }
        sxn[tid] = s;
    }
    __syncthreads();

    const int rw = warp >> 1, ch = warp & 1;
    uint4 afr[8];
    #pragma unroll
    for (int kk = 0; kk < 8; kk++)
        afr[kk] = *(const uint4*)&AP[((rw * 8 + kk) * 32 + lane) * 4];
    const float xn0 = sxn[rw * 16 + gid];
    const float xn1 = sxn[rw * 16 + gid + 8];

    for (int s = 0; s < 8; s++) {
        const int j0 = jbase + s * 128;
        __syncthreads();   // previous stage BP/syn fully consumed
        for (int e = tid; e < 8192; e += NTC) {
            const int r = e >> 6, c = e & 63;
            float v = __ldg(y + (size_t)(j0 + r) * 64 + c);
            unsigned tv; CVT_TF32(tv, v);
            const int t = r >> 3, g = r & 7, kk = c >> 3, rem = c & 7;
            BP[((t * 8 + kk) * 32 + g * 4 + (rem & 3)) * 2 + (rem >> 2)] = tv;
        }
        if (tid < 128) {
            const float4* yr = (const float4*)(y + (size_t)(j0 + tid) * 64);
            float sv = 0.f;
            #pragma unroll
            for (int q = 0; q < 16; q++) {
                float4 v = __ldg(yr + q);
                sv = fmaf(v.x, v.x, sv); sv = fmaf(v.y, v.y, sv);
                sv = fmaf(v.z, v.z, sv); sv = fmaf(v.w, v.w, sv);
            }
            syn[tid] = sv;
        }
        __syncthreads();

        #pragma unroll
        for (int tt = 0; tt < 8; tt++) {
            const int t = ch * 8 + tt;
            float c0 = 0.f, c1 = 0.f, c2 = 0.f, c3 = 0.f;
            #pragma unroll
            for (int kk = 0; kk < 8; kk++) {
                uint2 b = *(const uint2*)&BP[((t * 8 + kk) * 32 + lane) * 2];
                asm volatile(
                    "mma.sync.aligned.m16n8k8.row.col.f32.tf32.tf32.f32 "
                    "{%0,%1,%2,%3}, {%4,%5,%6,%7}, {%8,%9}, {%0,%1,%2,%3};"
                    : "+f"(c0), "+f"(c1), "+f"(c2), "+f"(c3)
                    : "r"(afr[kk].x), "r"(afr[kk].y), "r"(afr[kk].z), "r"(afr[kk].w),
                      "r"(b.x), "r"(b.y));
            }
            const int jc = t * 8 + 2 * tig;
            const float yn0 = syn[jc], yn1 = syn[jc + 1];
            float2 k01, k23;
            k01.x = fexp(-LAMDA * (xn0 + yn0 - 2.f * c0));
            k01.y = fexp(-LAMDA * (xn0 + yn1 - 2.f * c1));
            k23.x = fexp(-LAMDA * (xn1 + yn0 - 2.f * c2));
            k23.y = fexp(-LAMDA * (xn1 + yn1 - 2.f * c3));
            const int ig = i0 + rw * 16 + gid;
            *(float2*)(g_K + (size_t)ig * Mm + j0 + jc)       = k01;
            *(float2*)(g_K + (size_t)(ig + 8) * Mm + j0 + jc) = k23;
        }
    }
}

// ===================== Kernel 2: Sinkhorn loop (NT=1024, proven) ==========
__global__ void __launch_bounds__(NTS, 1)
sink_kernel(const float* __restrict__ mu, const float* __restrict__ nu) {
    __shared__ float  sA[Nn];
    __shared__ float  sB[Mm];
    __shared__ float  sred[NWS][33];
    __shared__ double sRow[NWS];
    __shared__ double sDS1[NWS];
    __shared__ double sDisp;

    const int tid = threadIdx.x, blk = blockIdx.x;
    const int warp = tid >> 5, lane = tid & 31;
    const unsigned FULL = 0xffffffffu;
    const unsigned base = __ldcg(&g_bar_cnt);
    unsigned gen = 0;
    int fpar = 0;

    for (int it = 0; it < MAX_ITER; ++it) {
        const int cur = it & 1, nxt = cur ^ 1;

        if (it > 0) {       // deferred convergence check on it-1
            if (warp == 0) {
                double sd = __ldcg(&g_bdisp[lane])      + __ldcg(&g_bdisp[lane + 32])
                          + __ldcg(&g_bdisp[lane + 64]) + __ldcg(&g_bdisp[lane + 96]);
                #pragma unroll
                for (int off = 16; off; off >>= 1)
                    sd += __shfl_down_sync(FULL, sd, off);
                if (lane == 0) sDisp = sd;
            }
            __syncthreads();
            if (sDisp <= STOP_THR) { fpar = cur; break; }
            __syncthreads();
        }

        // ---- Phase A: b[nxt] = nu / (K^T a[cur])
        for (int i = tid; i < Nn; i += NTS) sA[i] = __ldcg(&g_a[cur][i]);
        __syncthreads();
        {
            const int j = blk * 32 + lane;
            const float* Kc = g_K + j;
            float acc[8];
            #pragma unroll
            for (int u = 0; u < 8; u++) acc[u] = 0.f;
            for (int ib = 0; ib < Nn; ib += 256) {
                #pragma unroll
                for (int u = 0; u < 8; u++) {
                    const int i = ib + warp + 32 * u;
                    acc[u] = fmaf(Kc[(size_t)i * Mm], sA[i], acc[u]);
                }
            }
            float s = ((acc[0] + acc[1]) + (acc[2] + acc[3]))
                    + ((acc[4] + acc[5]) + (acc[6] + acc[7]));
            sred[warp][lane] = s;
        }
        __syncthreads();
        if (warp == 0) {
            float s = 0.f;
            #pragma unroll
            for (int w = 0; w < NWS; ++w) s += sred[w][lane];
            int j = blk * 32 + lane;
            g_b[nxt][j] = __ldg(&nu[j]) / s;
        }
        gbar(base + (++gen) * NB);

        // ---- Phase B: a[nxt] = mu/(K b_new) + fused disp (1 row per warp)
        for (int i = tid; i < Mm; i += NTS) sA[i] = __ldcg(&g_b[nxt][i]);
        for (int i = tid; i < Mm; i += NTS) sB[i] = __ldcg(&g_b[cur][i]);
        __syncthreads();
        {
            const int i = blk * 32 + warp;
            const ull* K2 = (const ull*)(g_K + (size_t)i * Mm);
            const ull* A2 = (const ull*)sA;
            const ull* B2 = (const ull*)sB;
            ull t = 0ULL, s1 = 0ULL, s2 = 0ULL;
            #pragma unroll 4
            for (int j = lane; j < Mm / 2; j += 32) {
                ull k = K2[j], bn = A2[j], be = B2[j];
                ull k2, tmp;
                MUL2(k2, k, k);
                FMA2(t, k, bn);
                MUL2(tmp, k2, bn);
                FMA2(s1, tmp, bn);
                FMA2(s2, tmp, be);
            }
            float l, h;
            UNPACK2(l, h, t);  float tf  = l + h;
            UNPACK2(l, h, s1); float s1f = l + h;
            UNPACK2(l, h, s2); float s2f = l + h;
            #pragma unroll
            for (int off = 16; off; off >>= 1) {
                tf  += __shfl_down_sync(FULL, tf,  off);
                s1f += __shfl_down_sync(FULL, s1f, off);
                s2f += __shfl_down_sync(FULL, s2f, off);
            }
            if (lane == 0) {
                float an = __ldg(&mu[i]) / tf;
                g_a[nxt][i] = an;
                double dan = (double)an;
                double dao = (double)__ldcg(&g_a[cur][i]);
                double dS1 = dan * dan * (double)s1f;
                double d = (it == 0)
                    ? dS1
                    : dS1 - 2.0 * dan * dao * (double)s2f + sDS1[warp];
                sDS1[warp] = dS1;
                sRow[warp] = d;
            }
        }
        __syncthreads();
        if (tid == 0) {
            double s = 0.0;
            #pragma unroll
            for (int q = 0; q < NWS; ++q) s += sRow[q];
            g_bdisp[blk] = s;
        }
        fpar = nxt;
        gbar(base + (++gen) * NB);
    }

    if (blk == 0 && tid == 0) g_final = fpar;
}

// ===================== Kernel 3: epilogue + last-block cost reduce ========
__global__ void __launch_bounds__(NTS, 1)
epi_kernel(float* __restrict__ out) {
    __shared__ float  sA[Mm];
    __shared__ float  sB[Mm];
    __shared__ double sRow[NWS];
    __shared__ int    sLast;

    const int tid = threadIdx.x, blk = blockIdx.x;
    const int warp = tid >> 5, lane = tid & 31;
    const unsigned FULL = 0xffffffffu;
    const int fpar = __ldcg(&g_final);

    float* Pout = out + 1;
    float* Cmat = out + 1 + (size_t)Nn * Mm;

    for (int i = tid; i < Mm; i += NTS) sA[i] = __ldcg(&g_b[fpar][i]);
    __syncthreads();
    for (int m = tid; m < Mm - 3; m += NTS) sB[m] = sA[m + 3];
    __syncthreads();
    const float4* Bsh4 = (const float4*)sB;

    {
        const int i = blk * 32 + warp;           // 1 row per warp
        const float ai = __ldcg(&g_a[fpar][i]);
        const float*  Kr = g_K + (size_t)i * Mm;
        const float4* K4 = (const float4*)Kr;
        float* Pr = Pout + (size_t)i * Mm;
        float* Cr = Cmat + (size_t)i * Mm;
        float csum = 0.f;

        if (lane < 3) {                  // head j = 0,1,2
            float k = Kr[lane];
            float p = ai * k * sA[lane];
            float c = -69.31471805599453f * __log2f(k);
            __stcs(Pr + lane, p);
            __stcs(Cr + lane, c);
            csum = fmaf(p, c, csum);
        }

        float4 curr = K4[lane];
        for (int s = 0; s < 32; s++) {
            const int q = lane + 32 * s;
            const int nidx = (s < 31) ? (lane + 32 * (s + 1)) : lane;
            float4 newq = K4[nidx];
            float nx = __shfl_down_sync(FULL, curr.x, 1);
            float ny = __shfl_down_sync(FULL, curr.y, 1);
            float nz = __shfl_down_sync(FULL, curr.z, 1);
            float bx = __shfl_sync(FULL, newq.x, 0);
            float by = __shfl_sync(FULL, newq.y, 0);
            float bz = __shfl_sync(FULL, newq.z, 0);
            if (lane == 31) { nx = bx; ny = by; nz = bz; }

            if (q <= 1022) {
                const int jst = 4 * q + 3;
                float k0 = curr.w, k1 = nx, k2 = ny, k3 = nz;
                float4 bq = Bsh4[q];
                float p0 = ai * k0 * bq.x, p1 = ai * k1 * bq.y;
                float p2 = ai * k2 * bq.z, p3 = ai * k3 * bq.w;
                float c0 = -69.31471805599453f * __log2f(k0);
                float c1 = -69.31471805599453f * __log2f(k1);
                float c2 = -69.31471805599453f * __log2f(k2);
                float c3 = -69.31471805599453f * __log2f(k3);
                float4 pq; pq.x = p0; pq.y = p1; pq.z = p2; pq.w = p3;
                float4 cq; cq.x = c0; cq.y = c1; cq.z = c2; cq.w = c3;
                __stcs((float4*)(Pr + jst), pq);
                __stcs((float4*)(Cr + jst), cq);
                csum = fmaf(p0, c0, csum); csum = fmaf(p1, c1, csum);
                csum = fmaf(p2, c2, csum); csum = fmaf(p3, c3, csum);
            }
            if (s == 31 && lane == 31) {  // tail j = 4095
                float k = curr.w;
                float p = ai * k * sA[4095];
                float c = -69.31471805599453f * __log2f(k);
                __stcs(Pr + 4095, p);
                __stcs(Cr + 4095, c);
                csum = fmaf(p, c, csum);
            }
            curr = newq;
        }

        #pragma unroll
        for (int off = 16; off; off >>= 1)
            csum += __shfl_down_sync(FULL, csum, off);
        if (lane == 0) sRow[warp] = (double)csum;
    }
    __syncthreads();
    if (tid == 0) {
        double s = 0.0;
        #pragma unroll
        for (int q = 0; q < NWS; ++q) s += sRow[q];
        g_bcost[blk] = s;
        __threadfence();
        unsigned old;
        asm volatile("atom.global.add.u32 %0, [%1], 1;"
                     : "=r"(old) : "l"(&g_epi_ticket) : "memory");
        sLast = ((old + 1) % NB == 0);
    }
    __syncthreads();
    if (sLast) {
        __threadfence();
        if (warp == 0) {
            double sc = __ldcg(&g_bcost[lane])      + __ldcg(&g_bcost[lane + 32])
                      + __ldcg(&g_bcost[lane + 64]) + __ldcg(&g_bcost[lane + 96]);
            #pragma unroll
            for (int off = 16; off; off >>= 1)
                sc += __shfl_down_sync(FULL, sc, off);
            if (lane == 0) out[0] = (float)sc;
        }
    }
}

// ---------------- launch ----------------
extern "C" void kernel_launch(void* const* d_in, const int* in_sizes, int n_in,
                              void* d_out, int out_size) {
    const float* x  = (const float*)d_in[0];
    const float* y  = (const float*)d_in[1];
    const float* mu = (const float*)d_in[2];
    const float* nu = (const float*)d_in[3];
    float* out = (float*)d_out;

    const int ck_smem = 16384 * (int)sizeof(unsigned) + 256 * (int)sizeof(float);
    cudaFuncSetAttribute(ck_kernel, cudaFuncAttributeMaxDynamicSharedMemorySize, ck_smem);

    ck_kernel<<<NB, NTC, ck_smem>>>(x, y);
    sink_kernel<<<NB, NTS>>>(mu, nu);
    epi_kernel<<<NB, NTS>>>(out);
}

// round 16
// speedup vs baseline: 1.3587x; 1.1525x over previous
#include <cuda_runtime.h>
#include <math.h>
#include <stdint.h>

#define Nn 4096
#define Mm 4096
#define LAMDA 0.01f
#define STOP_THR 1e-7
#define MAX_ITER 100
#define NB 128
#define NTC 512    // CK threads
#define NTS 1024   // sink/epi threads
#define NWS 32     // sink/epi warps

typedef unsigned long long ull;

// ---------------- device globals ----------------
__device__ float  g_K[(size_t)Nn * Mm];   // 64 MB fp32 K (L2-resident)
__device__ float  g_a[2][Nn];
__device__ float  g_b[2][Mm];
__device__ double g_bdisp[NB];
__device__ double g_bcost[NB];
__device__ int    g_final;
__device__ unsigned g_bar_cnt;     // monotonic
__device__ unsigned g_epi_ticket;  // monotonic

// ---------------- fast exp: FFMA-only ----------------
__device__ __forceinline__ float fexp(float xx) {
    float t  = fmaf(xx, 1.4426950408889634f, 12582912.0f);
    int   n  = __float_as_int(t) - 0x4B400000;
    float fn = t - 12582912.0f;
    float r  = fmaf(fn, -0.693145751953125f, xx);
    r        = fmaf(fn, -1.42860677e-6f, r);
    float p  = 1.3888890e-3f;
    p = fmaf(p, r, 8.3333338e-3f);
    p = fmaf(p, r, 4.1666668e-2f);
    p = fmaf(p, r, 1.6666667e-1f);
    p = fmaf(p, r, 5.0000000e-1f);
    p = fmaf(p, r, 1.0f);
    p = fmaf(p, r, 1.0f);
    return __int_as_float(__float_as_int(p) + (n << 23));
}

#define FMA2(d, a, b) \
    asm("fma.rn.f32x2 %0, %1, %2, %0;" : "+l"(d) : "l"(a), "l"(b))
#define MUL2(d, a, b) \
    asm("mul.rn.f32x2 %0, %1, %2;" : "=l"(d) : "l"(a), "l"(b))
#define UNPACK2(lo, hi, v) \
    asm("mov.b64 {%0, %1}, %2;" : "=f"(lo), "=f"(hi) : "l"(v))
#define CVT_TF32(d, f) \
    asm("cvt.rna.tf32.f32 %0, %1;" : "=r"(d) : "f"(f))

// ------------- cheap acquire/release grid barrier -------
__device__ __forceinline__ void red_rel_add1(unsigned* p) {
    asm volatile("red.release.gpu.global.add.u32 [%0], 1;" :: "l"(p) : "memory");
}
__device__ __forceinline__ unsigned ld_acq(unsigned* p) {
    unsigned v;
    asm volatile("ld.acquire.gpu.global.u32 %0, [%1];" : "=r"(v) : "l"(p) : "memory");
    return v;
}
__device__ __forceinline__ void gbar(unsigned target) {
    __syncthreads();
    if (threadIdx.x == 0) {
        red_rel_add1(&g_bar_cnt);
        while ((int)(ld_acq(&g_bar_cnt) - target) < 0) { }
    }
    __syncthreads();
}

// ===================== Kernel 1: CK build via tf32 MMA, pipelined =========
// Block: 128 rows (i0) x 1024 cols (jbase), 8 col-stages of 128.
// Double-buffered B fragments; next stage's y loads issued BEFORE this
// stage's MMA+fexp, stored to smem after -> global latency hidden.
// syn/sxn folded into the same loads (shfl-reduce over 4 lanes per row).
__global__ void __launch_bounds__(NTC, 1)
ck_kernel(const float* __restrict__ x, const float* __restrict__ y) {
    extern __shared__ unsigned smu[];
    unsigned* AP  = smu;                    // [8 rw][8 kk][32 ln][4 reg] = 8192
    unsigned* BP0 = smu + 8192;             // 8192
    unsigned* BP1 = smu + 16384;            // 8192
    float* sxn  = (float*)(smu + 24576);    // [128]
    float* syn0 = sxn + 128;                // [128]
    float* syn1 = syn0 + 128;               // [128]

    const int tid = threadIdx.x, blk = blockIdx.x;
    const int lane = tid & 31, warp = tid >> 5;
    const int gid = lane >> 2, tig = lane & 3;
    const unsigned FULL = 0xffffffffu;

    if (tid < 32) {
        g_a[0][blk * 32 + tid] = 1.0f / (float)Nn;
        g_b[0][blk * 32 + tid] = 1.0f;
    }

    const int i0 = (blk >> 2) * 128;
    const int jbase = (blk & 3) * 1024;

    const int pr = tid >> 2;          // packing: row 0..127
    const int pc0 = (tid & 3) * 16;   // packing: col base

    // ---- pack A fragments + sxn (vectorized, shfl-reduced)
    {
        const float4* xr = (const float4*)(x + (size_t)(i0 + pr) * 64 + pc0);
        float4 v0 = __ldg(xr), v1 = __ldg(xr + 1), v2 = __ldg(xr + 2), v3 = __ldg(xr + 3);
        float vv[16] = {v0.x, v0.y, v0.z, v0.w, v1.x, v1.y, v1.z, v1.w,
                        v2.x, v2.y, v2.z, v2.w, v3.x, v3.y, v3.z, v3.w};
        float ssq = 0.f;
        #pragma unroll
        for (int e = 0; e < 16; e++) ssq = fmaf(vv[e], vv[e], ssq);
        ssq += __shfl_xor_sync(FULL, ssq, 1);
        ssq += __shfl_xor_sync(FULL, ssq, 2);
        if ((tid & 3) == 0) sxn[pr] = ssq;
        const int rw = pr >> 4, ri = pr & 15;
        #pragma unroll
        for (int e = 0; e < 16; e++) {
            const int c = pc0 + e, kk = c >> 3, rem = c & 7;
            const int reg = (ri >> 3) + 2 * (rem >> 2);
            const int ln = (ri & 7) * 4 + (rem & 3);
            unsigned tv; CVT_TF32(tv, vv[e]);
            AP[((rw * 8 + kk) * 32 + ln) * 4 + reg] = tv;
        }
    }
    // ---- pack B stage 0
    {
        const float4* yr = (const float4*)(y + (size_t)(jbase + pr) * 64 + pc0);
        float4 v0 = __ldg(yr), v1 = __ldg(yr + 1), v2 = __ldg(yr + 2), v3 = __ldg(yr + 3);
        float vv[16] = {v0.x, v0.y, v0.z, v0.w, v1.x, v1.y, v1.z, v1.w,
                        v2.x, v2.y, v2.z, v2.w, v3.x, v3.y, v3.z, v3.w};
        float ssq = 0.f;
        #pragma unroll
        for (int e = 0; e < 16; e++) ssq = fmaf(vv[e], vv[e], ssq);
        ssq += __shfl_xor_sync(FULL, ssq, 1);
        ssq += __shfl_xor_sync(FULL, ssq, 2);
        if ((tid & 3) == 0) syn0[pr] = ssq;
        const int bt = pr >> 3, g = pr & 7;
        #pragma unroll
        for (int e = 0; e < 16; e++) {
            const int c = pc0 + e, kk = c >> 3, rem = c & 7;
            unsigned tv; CVT_TF32(tv, vv[e]);
            BP0[((bt * 8 + kk) * 32 + g * 4 + (rem & 3)) * 2 + (rem >> 2)] = tv;
        }
    }
    __syncthreads();

    const int rw = warp >> 1, ch = warp & 1;
    uint4 afr[8];
    #pragma unroll
    for (int kk = 0; kk < 8; kk++)
        afr[kk] = *(const uint4*)&AP[((rw * 8 + kk) * 32 + lane) * 4];
    const float xn0 = sxn[rw * 16 + gid];
    const float xn1 = sxn[rw * 16 + gid + 8];

    for (int s = 0; s < 8; s++) {
        const unsigned* BPc = (s & 1) ? BP1 : BP0;
        unsigned*       BPn = (s & 1) ? BP0 : BP1;
        const float*    sync_ = (s & 1) ? syn1 : syn0;
        float*          synn  = (s & 1) ? syn0 : syn1;
        const int j0 = jbase + s * 128;

        // ---- prefetch next stage's y into registers (latency overlapped)
        float4 v0, v1, v2, v3;
        if (s < 7) {
            const float4* yr = (const float4*)(y + (size_t)(j0 + 128 + pr) * 64 + pc0);
            v0 = __ldg(yr); v1 = __ldg(yr + 1); v2 = __ldg(yr + 2); v3 = __ldg(yr + 3);
        }

        // ---- MMA + fexp epilogue on current stage
        #pragma unroll
        for (int tt = 0; tt < 8; tt++) {
            const int t = ch * 8 + tt;
            float c0 = 0.f, c1 = 0.f, c2 = 0.f, c3 = 0.f;
            #pragma unroll
            for (int kk = 0; kk < 8; kk++) {
                uint2 b = *(const uint2*)&BPc[((t * 8 + kk) * 32 + lane) * 2];
                asm volatile(
                    "mma.sync.aligned.m16n8k8.row.col.f32.tf32.tf32.f32 "
                    "{%0,%1,%2,%3}, {%4,%5,%6,%7}, {%8,%9}, {%0,%1,%2,%3};"
                    : "+f"(c0), "+f"(c1), "+f"(c2), "+f"(c3)
                    : "r"(afr[kk].x), "r"(afr[kk].y), "r"(afr[kk].z), "r"(afr[kk].w),
                      "r"(b.x), "r"(b.y));
            }
            const int jc = t * 8 + 2 * tig;
            const float yn0 = sync_[jc], yn1 = sync_[jc + 1];
            float2 k01, k23;
            k01.x = fexp(-LAMDA * (xn0 + yn0 - 2.f * c0));
            k01.y = fexp(-LAMDA * (xn0 + yn1 - 2.f * c1));
            k23.x = fexp(-LAMDA * (xn1 + yn0 - 2.f * c2));
            k23.y = fexp(-LAMDA * (xn1 + yn1 - 2.f * c3));
            const int ig = i0 + rw * 16 + gid;
            *(float2*)(g_K + (size_t)ig * Mm + j0 + jc)       = k01;
            *(float2*)(g_K + (size_t)(ig + 8) * Mm + j0 + jc) = k23;
        }

        // ---- store prefetched stage into the other buffer
        if (s < 7) {
            float vv[16] = {v0.x, v0.y, v0.z, v0.w, v1.x, v1.y, v1.z, v1.w,
                            v2.x, v2.y, v2.z, v2.w, v3.x, v3.y, v3.z, v3.w};
            float ssq = 0.f;
            #pragma unroll
            for (int e = 0; e < 16; e++) ssq = fmaf(vv[e], vv[e], ssq);
            ssq += __shfl_xor_sync(FULL, ssq, 1);
            ssq += __shfl_xor_sync(FULL, ssq, 2);
            if ((tid & 3) == 0) synn[pr] = ssq;
            const int bt = pr >> 3, g = pr & 7;
            #pragma unroll
            for (int e = 0; e < 16; e++) {
                const int c = pc0 + e, kk = c >> 3, rem = c & 7;
                unsigned tv; CVT_TF32(tv, vv[e]);
                BPn[((bt * 8 + kk) * 32 + g * 4 + (rem & 3)) * 2 + (rem >> 2)] = tv;
            }
        }
        __syncthreads();
    }
}

// ===================== Kernel 2: Sinkhorn loop (NT=1024, proven) ==========
__global__ void __launch_bounds__(NTS, 1)
sink_kernel(const float* __restrict__ mu, const float* __restrict__ nu) {
    __shared__ float  sA[Nn];
    __shared__ float  sB[Mm];
    __shared__ float  sred[NWS][33];
    __shared__ double sRow[NWS];
    __shared__ double sDS1[NWS];
    __shared__ double sDisp;

    const int tid = threadIdx.x, blk = blockIdx.x;
    const int warp = tid >> 5, lane = tid & 31;
    const unsigned FULL = 0xffffffffu;
    const unsigned base = __ldcg(&g_bar_cnt);
    unsigned gen = 0;
    int fpar = 0;

    for (int it = 0; it < MAX_ITER; ++it) {
        const int cur = it & 1, nxt = cur ^ 1;

        if (it > 0) {       // deferred convergence check on it-1
            if (warp == 0) {
                double sd = __ldcg(&g_bdisp[lane])      + __ldcg(&g_bdisp[lane + 32])
                          + __ldcg(&g_bdisp[lane + 64]) + __ldcg(&g_bdisp[lane + 96]);
                #pragma unroll
                for (int off = 16; off; off >>= 1)
                    sd += __shfl_down_sync(FULL, sd, off);
                if (lane == 0) sDisp = sd;
            }
            __syncthreads();
            if (sDisp <= STOP_THR) { fpar = cur; break; }
            __syncthreads();
        }

        // ---- Phase A: b[nxt] = nu / (K^T a[cur])
        for (int i = tid; i < Nn; i += NTS) sA[i] = __ldcg(&g_a[cur][i]);
        __syncthreads();
        {
            const int j = blk * 32 + lane;
            const float* Kc = g_K + j;
            float acc[8];
            #pragma unroll
            for (int u = 0; u < 8; u++) acc[u] = 0.f;
            for (int ib = 0; ib < Nn; ib += 256) {
                #pragma unroll
                for (int u = 0; u < 8; u++) {
                    const int i = ib + warp + 32 * u;
                    acc[u] = fmaf(Kc[(size_t)i * Mm], sA[i], acc[u]);
                }
            }
            float s = ((acc[0] + acc[1]) + (acc[2] + acc[3]))
                    + ((acc[4] + acc[5]) + (acc[6] + acc[7]));
            sred[warp][lane] = s;
        }
        __syncthreads();
        if (warp == 0) {
            float s = 0.f;
            #pragma unroll
            for (int w = 0; w < NWS; ++w) s += sred[w][lane];
            int j = blk * 32 + lane;
            g_b[nxt][j] = __ldg(&nu[j]) / s;
        }
        gbar(base + (++gen) * NB);

        // ---- Phase B: a[nxt] = mu/(K b_new) + fused disp (1 row per warp)
        for (int i = tid; i < Mm; i += NTS) sA[i] = __ldcg(&g_b[nxt][i]);
        for (int i = tid; i < Mm; i += NTS) sB[i] = __ldcg(&g_b[cur][i]);
        __syncthreads();
        {
            const int i = blk * 32 + warp;
            const ull* K2 = (const ull*)(g_K + (size_t)i * Mm);
            const ull* A2 = (const ull*)sA;
            const ull* B2 = (const ull*)sB;
            ull t = 0ULL, s1 = 0ULL, s2 = 0ULL;
            #pragma unroll 4
            for (int j = lane; j < Mm / 2; j += 32) {
                ull k = K2[j], bn = A2[j], be = B2[j];
                ull k2, tmp;
                MUL2(k2, k, k);
                FMA2(t, k, bn);
                MUL2(tmp, k2, bn);
                FMA2(s1, tmp, bn);
                FMA2(s2, tmp, be);
            }
            float l, h;
            UNPACK2(l, h, t);  float tf  = l + h;
            UNPACK2(l, h, s1); float s1f = l + h;
            UNPACK2(l, h, s2); float s2f = l + h;
            #pragma unroll
            for (int off = 16; off; off >>= 1) {
                tf  += __shfl_down_sync(FULL, tf,  off);
                s1f += __shfl_down_sync(FULL, s1f, off);
                s2f += __shfl_down_sync(FULL, s2f, off);
            }
            if (lane == 0) {
                float an = __ldg(&mu[i]) / tf;
                g_a[nxt][i] = an;
                double dan = (double)an;
                double dao = (double)__ldcg(&g_a[cur][i]);
                double dS1 = dan * dan * (double)s1f;
                double d = (it == 0)
                    ? dS1
                    : dS1 - 2.0 * dan * dao * (double)s2f + sDS1[warp];
                sDS1[warp] = dS1;
                sRow[warp] = d;
            }
        }
        __syncthreads();
        if (tid == 0) {
            double s = 0.0;
            #pragma unroll
            for (int q = 0; q < NWS; ++q) s += sRow[q];
            g_bdisp[blk] = s;
        }
        fpar = nxt;
        gbar(base + (++gen) * NB);
    }

    if (blk == 0 && tid == 0) g_final = fpar;
}

// ===================== Kernel 3: epilogue + last-block cost reduce ========
__global__ void __launch_bounds__(NTS, 1)
epi_kernel(float* __restrict__ out) {
    __shared__ float  sA[Mm];
    __shared__ float  sB[Mm];
    __shared__ double sRow[NWS];
    __shared__ int    sLast;

    const int tid = threadIdx.x, blk = blockIdx.x;
    const int warp = tid >> 5, lane = tid & 31;
    const unsigned FULL = 0xffffffffu;
    const int fpar = __ldcg(&g_final);

    float* Pout = out + 1;
    float* Cmat = out + 1 + (size_t)Nn * Mm;

    for (int i = tid; i < Mm; i += NTS) sA[i] = __ldcg(&g_b[fpar][i]);
    __syncthreads();
    for (int m = tid; m < Mm - 3; m += NTS) sB[m] = sA[m + 3];
    __syncthreads();
    const float4* Bsh4 = (const float4*)sB;

    {
        const int i = blk * 32 + warp;           // 1 row per warp
        const float ai = __ldcg(&g_a[fpar][i]);
        const float*  Kr = g_K + (size_t)i * Mm;
        const float4* K4 = (const float4*)Kr;
        float* Pr = Pout + (size_t)i * Mm;
        float* Cr = Cmat + (size_t)i * Mm;
        float csum = 0.f;

        if (lane < 3) {                  // head j = 0,1,2
            float k = Kr[lane];
            float p = ai * k * sA[lane];
            float c = -69.31471805599453f * __log2f(k);
            __stcs(Pr + lane, p);
            __stcs(Cr + lane, c);
            csum = fmaf(p, c, csum);
        }

        float4 curr = K4[lane];
        for (int s = 0; s < 32; s++) {
            const int q = lane + 32 * s;
            const int nidx = (s < 31) ? (lane + 32 * (s + 1)) : lane;
            float4 newq = K4[nidx];
            float nx = __shfl_down_sync(FULL, curr.x, 1);
            float ny = __shfl_down_sync(FULL, curr.y, 1);
            float nz = __shfl_down_sync(FULL, curr.z, 1);
            float bx = __shfl_sync(FULL, newq.x, 0);
            float by = __shfl_sync(FULL, newq.y, 0);
            float bz = __shfl_sync(FULL, newq.z, 0);
            if (lane == 31) { nx = bx; ny = by; nz = bz; }

            if (q <= 1022) {
                const int jst = 4 * q + 3;
                float k0 = curr.w, k1 = nx, k2 = ny, k3 = nz;
                float4 bq = Bsh4[q];
                float p0 = ai * k0 * bq.x, p1 = ai * k1 * bq.y;
                float p2 = ai * k2 * bq.z, p3 = ai * k3 * bq.w;
                float c0 = -69.31471805599453f * __log2f(k0);
                float c1 = -69.31471805599453f * __log2f(k1);
                float c2 = -69.31471805599453f * __log2f(k2);
                float c3 = -69.31471805599453f * __log2f(k3);
                float4 pq; pq.x = p0; pq.y = p1; pq.z = p2; pq.w = p3;
                float4 cq; cq.x = c0; cq.y = c1; cq.z = c2; cq.w = c3;
                __stcs((float4*)(Pr + jst), pq);
                __stcs((float4*)(Cr + jst), cq);
                csum = fmaf(p0, c0, csum); csum = fmaf(p1, c1, csum);
                csum = fmaf(p2, c2, csum); csum = fmaf(p3, c3, csum);
            }
            if (s == 31 && lane == 31) {  // tail j = 4095
                float k = curr.w;
                float p = ai * k * sA[4095];
                float c = -69.31471805599453f * __log2f(k);
                __stcs(Pr + 4095, p);
                __stcs(Cr + 4095, c);
                csum = fmaf(p, c, csum);
            }
            curr = newq;
        }

        #pragma unroll
        for (int off = 16; off; off >>= 1)
            csum += __shfl_down_sync(FULL, csum, off);
        if (lane == 0) sRow[warp] = (double)csum;
    }
    __syncthreads();
    if (tid == 0) {
        double s = 0.0;
        #pragma unroll
        for (int q = 0; q < NWS; ++q) s += sRow[q];
        g_bcost[blk] = s;
        __threadfence();
        unsigned old;
        asm volatile("atom.global.add.u32 %0, [%1], 1;"
                     : "=r"(old) : "l"(&g_epi_ticket) : "memory");
        sLast = ((old + 1) % NB == 0);
    }
    __syncthreads();
    if (sLast) {
        __threadfence();
        if (warp == 0) {
            double sc = __ldcg(&g_bcost[lane])      + __ldcg(&g_bcost[lane + 32])
                      + __ldcg(&g_bcost[lane + 64]) + __ldcg(&g_bcost[lane + 96]);
            #pragma unroll
            for (int off = 16; off; off >>= 1)
                sc += __shfl_down_sync(FULL, sc, off);
            if (lane == 0) out[0] = (float)sc;
        }
    }
}

// ---------------- launch ----------------
extern "C" void kernel_launch(void* const* d_in, const int* in_sizes, int n_in,
                              void* d_out, int out_size) {
    const float* x  = (const float*)d_in[0];
    const float* y  = (const float*)d_in[1];
    const float* mu = (const float*)d_in[2];
    const float* nu = (const float*)d_in[3];
    float* out = (float*)d_out;

    const int ck_smem = 24576 * (int)sizeof(unsigned) + 384 * (int)sizeof(float);
    cudaFuncSetAttribute(ck_kernel, cudaFuncAttributeMaxDynamicSharedMemorySize, ck_smem);

    ck_kernel<<<NB, NTC, ck_smem>>>(x, y);
    sink_kernel<<<NB, NTS>>>(mu, nu);
    epi_kernel<<<NB, NTS>>>(out);
}

// round 17
// speedup vs baseline: 1.4307x; 1.0530x over previous
#include <cuda_runtime.h>
#include <math.h>
#include <stdint.h>

#define Nn 4096
#define Mm 4096
#define LAMDA 0.01f
#define STOP_THR 1e-7
#define MAX_ITER 100
#define NB 128
#define NTC 512    // CK threads
#define NTS 1024   // sink threads
#define NWS 32     // sink warps
#define SKK 66     // B-fragment group stride in uints (bank-conflict pad)

typedef unsigned long long ull;

// ---------------- device globals ----------------
__device__ float  g_K[(size_t)Nn * Mm];   // 64 MB fp32 K (L2-resident)
__device__ float  g_a[2][Nn];
__device__ float  g_b[2][Mm];
__device__ double g_bdisp[NB];
__device__ double g_bcost[NB];
__device__ unsigned g_bar_cnt;     // monotonic

// ---------------- fast exp: FFMA-only ----------------
__device__ __forceinline__ float fexp(float xx) {
    float t  = fmaf(xx, 1.4426950408889634f, 12582912.0f);
    int   n  = __float_as_int(t) - 0x4B400000;
    float fn = t - 12582912.0f;
    float r  = fmaf(fn, -0.693145751953125f, xx);
    r        = fmaf(fn, -1.42860677e-6f, r);
    float p  = 1.3888890e-3f;
    p = fmaf(p, r, 8.3333338e-3f);
    p = fmaf(p, r, 4.1666668e-2f);
    p = fmaf(p, r, 1.6666667e-1f);
    p = fmaf(p, r, 5.0000000e-1f);
    p = fmaf(p, r, 1.0f);
    p = fmaf(p, r, 1.0f);
    return __int_as_float(__float_as_int(p) + (n << 23));
}

#define FMA2(d, a, b) \
    asm("fma.rn.f32x2 %0, %1, %2, %0;" : "+l"(d) : "l"(a), "l"(b))
#define MUL2(d, a, b) \
    asm("mul.rn.f32x2 %0, %1, %2;" : "=l"(d) : "l"(a), "l"(b))
#define UNPACK2(lo, hi, v) \
    asm("mov.b64 {%0, %1}, %2;" : "=f"(lo), "=f"(hi) : "l"(v))
#define CVT_TF32(d, f) \
    asm("cvt.rna.tf32.f32 %0, %1;" : "=r"(d) : "f"(f))

// ------------- cheap acquire/release grid barrier -------
__device__ __forceinline__ void red_rel_add1(unsigned* p) {
    asm volatile("red.release.gpu.global.add.u32 [%0], 1;" :: "l"(p) : "memory");
}
__device__ __forceinline__ unsigned ld_acq(unsigned* p) {
    unsigned v;
    asm volatile("ld.acquire.gpu.global.u32 %0, [%1];" : "=r"(v) : "l"(p) : "memory");
    return v;
}
__device__ __forceinline__ void gbar(unsigned target) {
    __syncthreads();
    if (threadIdx.x == 0) {
        red_rel_add1(&g_bar_cnt);
        while ((int)(ld_acq(&g_bar_cnt) - target) < 0) { }
    }
    __syncthreads();
}

// ===================== Kernel 1: CK build via tf32 MMA, pipelined =========
// Same structure as the 124us kernel; B-fragment group stride padded
// 64 -> 66 uints so packing STS drops from 4-way to 2-way bank conflicts.
__global__ void __launch_bounds__(NTC, 1)
ck_kernel(const float* __restrict__ x, const float* __restrict__ y) {
    extern __shared__ unsigned smu[];
    unsigned* AP  = smu;                    // 8192 (A frags, stride 64 kept)
    unsigned* BP0 = smu + 8192;             // 128 groups * SKK
    unsigned* BP1 = BP0 + 128 * SKK;
    float* sxn  = (float*)(BP1 + 128 * SKK);  // [128]
    float* syn0 = sxn + 128;
    float* syn1 = syn0 + 128;

    const int tid = threadIdx.x, blk = blockIdx.x;
    const int lane = tid & 31, warp = tid >> 5;
    const int gid = lane >> 2, tig = lane & 3;
    const unsigned FULL = 0xffffffffu;

    if (tid < 32) {
        g_a[0][blk * 32 + tid] = 1.0f / (float)Nn;
        g_b[0][blk * 32 + tid] = 1.0f;
    }

    const int i0 = (blk >> 2) * 128;
    const int jbase = (blk & 3) * 1024;

    const int pr = tid >> 2;          // packing: row 0..127
    const int pc0 = (tid & 3) * 16;   // packing: col base

    // ---- pack A fragments + sxn
    {
        const float4* xr = (const float4*)(x + (size_t)(i0 + pr) * 64 + pc0);
        float4 v0 = __ldg(xr), v1 = __ldg(xr + 1), v2 = __ldg(xr + 2), v3 = __ldg(xr + 3);
        float vv[16] = {v0.x, v0.y, v0.z, v0.w, v1.x, v1.y, v1.z, v1.w,
                        v2.x, v2.y, v2.z, v2.w, v3.x, v3.y, v3.z, v3.w};
        float ssq = 0.f;
        #pragma unroll
        for (int e = 0; e < 16; e++) ssq = fmaf(vv[e], vv[e], ssq);
        ssq += __shfl_xor_sync(FULL, ssq, 1);
        ssq += __shfl_xor_sync(FULL, ssq, 2);
        if ((tid & 3) == 0) sxn[pr] = ssq;
        const int rw = pr >> 4, ri = pr & 15;
        #pragma unroll
        for (int e = 0; e < 16; e++) {
            const int c = pc0 + e, kk = c >> 3, rem = c & 7;
            const int reg = (ri >> 3) + 2 * (rem >> 2);
            const int ln = (ri & 7) * 4 + (rem & 3);
            unsigned tv; CVT_TF32(tv, vv[e]);
            AP[((rw * 8 + kk) * 32 + ln) * 4 + reg] = tv;
        }
    }
    // ---- pack B stage 0
    {
        const float4* yr = (const float4*)(y + (size_t)(jbase + pr) * 64 + pc0);
        float4 v0 = __ldg(yr), v1 = __ldg(yr + 1), v2 = __ldg(yr + 2), v3 = __ldg(yr + 3);
        float vv[16] = {v0.x, v0.y, v0.z, v0.w, v1.x, v1.y, v1.z, v1.w,
                        v2.x, v2.y, v2.z, v2.w, v3.x, v3.y, v3.z, v3.w};
        float ssq = 0.f;
        #pragma unroll
        for (int e = 0; e < 16; e++) ssq = fmaf(vv[e], vv[e], ssq);
        ssq += __shfl_xor_sync(FULL, ssq, 1);
        ssq += __shfl_xor_sync(FULL, ssq, 2);
        if ((tid & 3) == 0) syn0[pr] = ssq;
        const int bt = pr >> 3, g = pr & 7;
        #pragma unroll
        for (int e = 0; e < 16; e++) {
            const int c = pc0 + e, kk = c >> 3, rem = c & 7;
            unsigned tv; CVT_TF32(tv, vv[e]);
            BP0[(bt * 8 + kk) * SKK + g * 8 + (rem & 3) * 2 + (rem >> 2)] = tv;
        }
    }
    __syncthreads();

    const int rw = warp >> 1, ch = warp & 1;
    uint4 afr[8];
    #pragma unroll
    for (int kk = 0; kk < 8; kk++)
        afr[kk] = *(const uint4*)&AP[((rw * 8 + kk) * 32 + lane) * 4];
    const float xn0 = sxn[rw * 16 + gid];
    const float xn1 = sxn[rw * 16 + gid + 8];

    for (int s = 0; s < 8; s++) {
        const unsigned* BPc = (s & 1) ? BP1 : BP0;
        unsigned*       BPn = (s & 1) ? BP0 : BP1;
        const float*    sync_ = (s & 1) ? syn1 : syn0;
        float*          synn  = (s & 1) ? syn0 : syn1;
        const int j0 = jbase + s * 128;

        // ---- prefetch next stage's y into registers
        float4 v0, v1, v2, v3;
        if (s < 7) {
            const float4* yr = (const float4*)(y + (size_t)(j0 + 128 + pr) * 64 + pc0);
            v0 = __ldg(yr); v1 = __ldg(yr + 1); v2 = __ldg(yr + 2); v3 = __ldg(yr + 3);
        }

        // ---- MMA + fexp epilogue
        #pragma unroll
        for (int tt = 0; tt < 8; tt++) {
            const int t = ch * 8 + tt;
            float c0 = 0.f, c1 = 0.f, c2 = 0.f, c3 = 0.f;
            #pragma unroll
            for (int kk = 0; kk < 8; kk++) {
                uint2 b = *(const uint2*)&BPc[(t * 8 + kk) * SKK + lane * 2];
                asm volatile(
                    "mma.sync.aligned.m16n8k8.row.col.f32.tf32.tf32.f32 "
                    "{%0,%1,%2,%3}, {%4,%5,%6,%7}, {%8,%9}, {%0,%1,%2,%3};"
                    : "+f"(c0), "+f"(c1), "+f"(c2), "+f"(c3)
                    : "r"(afr[kk].x), "r"(afr[kk].y), "r"(afr[kk].z), "r"(afr[kk].w),
                      "r"(b.x), "r"(b.y));
            }
            const int jc = t * 8 + 2 * tig;
            const float yn0 = sync_[jc], yn1 = sync_[jc + 1];
            float2 k01, k23;
            k01.x = fexp(-LAMDA * (xn0 + yn0 - 2.f * c0));
            k01.y = fexp(-LAMDA * (xn0 + yn1 - 2.f * c1));
            k23.x = fexp(-LAMDA * (xn1 + yn0 - 2.f * c2));
            k23.y = fexp(-LAMDA * (xn1 + yn1 - 2.f * c3));
            const int ig = i0 + rw * 16 + gid;
            *(float2*)(g_K + (size_t)ig * Mm + j0 + jc)       = k01;
            *(float2*)(g_K + (size_t)(ig + 8) * Mm + j0 + jc) = k23;
        }

        // ---- store prefetched stage
        if (s < 7) {
            float vv[16] = {v0.x, v0.y, v0.z, v0.w, v1.x, v1.y, v1.z, v1.w,
                            v2.x, v2.y, v2.z, v2.w, v3.x, v3.y, v3.z, v3.w};
            float ssq = 0.f;
            #pragma unroll
            for (int e = 0; e < 16; e++) ssq = fmaf(vv[e], vv[e], ssq);
            ssq += __shfl_xor_sync(FULL, ssq, 1);
            ssq += __shfl_xor_sync(FULL, ssq, 2);
            if ((tid & 3) == 0) synn[pr] = ssq;
            const int bt = pr >> 3, g = pr & 7;
            #pragma unroll
            for (int e = 0; e < 16; e++) {
                const int c = pc0 + e, kk = c >> 3, rem = c & 7;
                unsigned tv; CVT_TF32(tv, vv[e]);
                BPn[(bt * 8 + kk) * SKK + g * 8 + (rem & 3) * 2 + (rem >> 2)] = tv;
            }
        }
        __syncthreads();
    }
}

// ===================== Kernel 2: Sinkhorn loop + fused epilogue ===========
__global__ void __launch_bounds__(NTS, 1)
sink_kernel(const float* __restrict__ mu, const float* __restrict__ nu,
            float* __restrict__ out) {
    __shared__ float  sA[Nn];
    __shared__ float  sB[Mm];
    __shared__ float  sred[NWS][33];
    __shared__ double sRow[NWS];
    __shared__ double sDS1[NWS];
    __shared__ double sDisp;

    const int tid = threadIdx.x, blk = blockIdx.x;
    const int warp = tid >> 5, lane = tid & 31;
    const unsigned FULL = 0xffffffffu;
    const unsigned base = __ldcg(&g_bar_cnt);
    unsigned gen = 0;
    int fpar = 0;

    for (int it = 0; it < MAX_ITER; ++it) {
        const int cur = it & 1, nxt = cur ^ 1;

        if (it > 0) {       // deferred convergence check on it-1
            if (warp == 0) {
                double sd = __ldcg(&g_bdisp[lane])      + __ldcg(&g_bdisp[lane + 32])
                          + __ldcg(&g_bdisp[lane + 64]) + __ldcg(&g_bdisp[lane + 96]);
                #pragma unroll
                for (int off = 16; off; off >>= 1)
                    sd += __shfl_down_sync(FULL, sd, off);
                if (lane == 0) sDisp = sd;
            }
            __syncthreads();
            if (sDisp <= STOP_THR) { fpar = cur; break; }
            __syncthreads();
        }

        // ---- Phase A: b[nxt] = nu / (K^T a[cur])
        for (int i = tid; i < Nn; i += NTS) sA[i] = __ldcg(&g_a[cur][i]);
        __syncthreads();
        {
            const int j = blk * 32 + lane;
            const float* Kc = g_K + j;
            float acc[8];
            #pragma unroll
            for (int u = 0; u < 8; u++) acc[u] = 0.f;
            for (int ib = 0; ib < Nn; ib += 256) {
                #pragma unroll
                for (int u = 0; u < 8; u++) {
                    const int i = ib + warp + 32 * u;
                    acc[u] = fmaf(Kc[(size_t)i * Mm], sA[i], acc[u]);
                }
            }
            float s = ((acc[0] + acc[1]) + (acc[2] + acc[3]))
                    + ((acc[4] + acc[5]) + (acc[6] + acc[7]));
            sred[warp][lane] = s;
        }
        __syncthreads();
        if (warp == 0) {
            float s = 0.f;
            #pragma unroll
            for (int w = 0; w < NWS; ++w) s += sred[w][lane];
            int j = blk * 32 + lane;
            g_b[nxt][j] = __ldg(&nu[j]) / s;
        }
        gbar(base + (++gen) * NB);

        // ---- Phase B: a[nxt] = mu/(K b_new) + fused disp (1 row per warp)
        for (int i = tid; i < Mm; i += NTS) sA[i] = __ldcg(&g_b[nxt][i]);
        for (int i = tid; i < Mm; i += NTS) sB[i] = __ldcg(&g_b[cur][i]);
        __syncthreads();
        {
            const int i = blk * 32 + warp;
            const ull* K2 = (const ull*)(g_K + (size_t)i * Mm);
            const ull* A2 = (const ull*)sA;
            const ull* B2 = (const ull*)sB;
            ull t = 0ULL, s1 = 0ULL, s2 = 0ULL;
            #pragma unroll 4
            for (int j = lane; j < Mm / 2; j += 32) {
                ull k = K2[j], bn = A2[j], be = B2[j];
                ull k2, tmp;
                MUL2(k2, k, k);
                FMA2(t, k, bn);
                MUL2(tmp, k2, bn);
                FMA2(s1, tmp, bn);
                FMA2(s2, tmp, be);
            }
            float l, h;
            UNPACK2(l, h, t);  float tf  = l + h;
            UNPACK2(l, h, s1); float s1f = l + h;
            UNPACK2(l, h, s2); float s2f = l + h;
            #pragma unroll
            for (int off = 16; off; off >>= 1) {
                tf  += __shfl_down_sync(FULL, tf,  off);
                s1f += __shfl_down_sync(FULL, s1f, off);
                s2f += __shfl_down_sync(FULL, s2f, off);
            }
            if (lane == 0) {
                float an = __ldg(&mu[i]) / tf;
                g_a[nxt][i] = an;
                double dan = (double)an;
                double dao = (double)__ldcg(&g_a[cur][i]);
                double dS1 = dan * dan * (double)s1f;
                double d = (it == 0)
                    ? dS1
                    : dS1 - 2.0 * dan * dao * (double)s2f + sDS1[warp];
                sDS1[warp] = dS1;
                sRow[warp] = d;
            }
        }
        __syncthreads();
        if (tid == 0) {
            double s = 0.0;
            #pragma unroll
            for (int q = 0; q < NWS; ++q) s += sRow[q];
            g_bdisp[blk] = s;
        }
        fpar = nxt;
        gbar(base + (++gen) * NB);
    }

    // ================= fused epilogue: P, C, cost =========================
    float* Pout = out + 1;
    float* Cmat = out + 1 + (size_t)Nn * Mm;

    __syncthreads();
    for (int i = tid; i < Mm; i += NTS) sA[i] = __ldcg(&g_b[fpar][i]);
    __syncthreads();
    for (int m = tid; m < Mm - 3; m += NTS) sB[m] = sA[m + 3];
    __syncthreads();
    const float4* Bsh4 = (const float4*)sB;

    {
        const int i = blk * 32 + warp;           // 1 row per warp
        const float ai = __ldcg(&g_a[fpar][i]);
        const float*  Kr = g_K + (size_t)i * Mm;
        const float4* K4 = (const float4*)Kr;
        float* Pr = Pout + (size_t)i * Mm;
        float* Cr = Cmat + (size_t)i * Mm;
        float csum = 0.f;

        if (lane < 3) {                  // head j = 0,1,2
            float k = Kr[lane];
            float p = ai * k * sA[lane];
            float c = -69.31471805599453f * __log2f(k);
            __stcs(Pr + lane, p);
            __stcs(Cr + lane, c);
            csum = fmaf(p, c, csum);
        }

        float4 curr = K4[lane];
        for (int s = 0; s < 32; s++) {
            const int q = lane + 32 * s;
            const int nidx = (s < 31) ? (lane + 32 * (s + 1)) : lane;
            float4 newq = K4[nidx];
            float nx = __shfl_down_sync(FULL, curr.x, 1);
            float ny = __shfl_down_sync(FULL, curr.y, 1);
            float nz = __shfl_down_sync(FULL, curr.z, 1);
            float bx = __shfl_sync(FULL, newq.x, 0);
            float by = __shfl_sync(FULL, newq.y, 0);
            float bz = __shfl_sync(FULL, newq.z, 0);
            if (lane == 31) { nx = bx; ny = by; nz = bz; }

            if (q <= 1022) {
                const int jst = 4 * q + 3;
                float k0 = curr.w, k1 = nx, k2 = ny, k3 = nz;
                float4 bq = Bsh4[q];
                float p0 = ai * k0 * bq.x, p1 = ai * k1 * bq.y;
                float p2 = ai * k2 * bq.z, p3 = ai * k3 * bq.w;
                float c0 = -69.31471805599453f * __log2f(k0);
                float c1 = -69.31471805599453f * __log2f(k1);
                float c2 = -69.31471805599453f * __log2f(k2);
                float c3 = -69.31471805599453f * __log2f(k3);
                float4 pq; pq.x = p0; pq.y = p1; pq.z = p2; pq.w = p3;
                float4 cq; cq.x = c0; cq.y = c1; cq.z = c2; cq.w = c3;
                __stcs((float4*)(Pr + jst), pq);
                __stcs((float4*)(Cr + jst), cq);
                csum = fmaf(p0, c0, csum); csum = fmaf(p1, c1, csum);
                csum = fmaf(p2, c2, csum); csum = fmaf(p3, c3, csum);
            }
            if (s == 31 && lane == 31) {  // tail j = 4095
                float k = curr.w;
                float p = ai * k * sA[4095];
                float c = -69.31471805599453f * __log2f(k);
                __stcs(Pr + 4095, p);
                __stcs(Cr + 4095, c);
                csum = fmaf(p, c, csum);
            }
            curr = newq;
        }

        #pragma unroll
        for (int off = 16; off; off >>= 1)
            csum += __shfl_down_sync(FULL, csum, off);
        if (lane == 0) sRow[warp] = (double)csum;
    }
    __syncthreads();
    if (tid == 0) {
        double s = 0.0;
        #pragma unroll
        for (int q = 0; q < NWS; ++q) s += sRow[q];
        g_bcost[blk] = s;
    }
    gbar(base + (++gen) * NB);
    if (blk == 0 && warp == 0) {
        double sc = __ldcg(&g_bcost[lane])      + __ldcg(&g_bcost[lane + 32])
                  + __ldcg(&g_bcost[lane + 64]) + __ldcg(&g_bcost[lane + 96]);
        #pragma unroll
        for (int off = 16; off; off >>= 1)
            sc += __shfl_down_sync(FULL, sc, off);
        if (lane == 0) out[0] = (float)sc;
    }
}

// ---------------- launch ----------------
extern "C" void kernel_launch(void* const* d_in, const int* in_sizes, int n_in,
                              void* d_out, int out_size) {
    const float* x  = (const float*)d_in[0];
    const float* y  = (const float*)d_in[1];
    const float* mu = (const float*)d_in[2];
    const float* nu = (const float*)d_in[3];
    float* out = (float*)d_out;

    const int ck_smem = (8192 + 2 * 128 * SKK) * (int)sizeof(unsigned)
                      + 384 * (int)sizeof(float);
    cudaFuncSetAttribute(ck_kernel, cudaFuncAttributeMaxDynamicSharedMemorySize, ck_smem);

    ck_kernel<<<NB, NTC, ck_smem>>>(x, y);
    sink_kernel<<<NB, NTS>>>(mu, nu, out);
}